// round 3
// baseline (speedup 1.0000x reference)
#include <cuda_runtime.h>
#include <math.h>

#define B_ 2
#define T_ 2048
#define E_ 1024
#define H_ 16
#define D_ 64
#define M_ (B_*T_)      /* 4096 rows */
#define N_ 1024         /* H*D == E */
#define K_ 1024

// Scratch (allocation-free rule: __device__ globals)
__device__ float g_q[M_*N_];
__device__ float g_k[M_*N_];
__device__ float g_v[M_*N_];
__device__ float g_z[M_*N_];
__device__ int   g_mask_is_byte;

// ---------------------------------------------------------------------------
// Mask dtype detection: bool may arrive as 1-byte (u8/i8) or 4-byte (i32/f32).
// 4-byte storage -> every word is 0, 1, or 0x3F800000 (1.0f).
// 1-byte storage -> packed 0/1 bytes make other word values with prob ~1.
// ---------------------------------------------------------------------------
__global__ void detect_mask_kernel(const unsigned int* __restrict__ w) {
    __shared__ int bad;
    if (threadIdx.x == 0) bad = 0;
    __syncthreads();
    int local = 0;
    for (int i = threadIdx.x; i < 4096; i += blockDim.x) {
        unsigned int x = w[i];
        if (x != 0u && x != 1u && x != 0x3F800000u) local = 1;
    }
    if (local) atomicOr(&bad, 1);
    __syncthreads();
    if (threadIdx.x == 0) g_mask_is_byte = bad;
}

// ---------------------------------------------------------------------------
// SGEMM: C[M,N] = A[M,K] @ W[K,N] + bias   (M=4096, N=K=1024, all /128,/16)
// 128x128 block tile, BK=16, 256 threads, 8x8 per-thread microtile.
// ---------------------------------------------------------------------------
__global__ __launch_bounds__(256) void sgemm_bias(
    const float* __restrict__ A, const float* __restrict__ W,
    const float* __restrict__ bias, float* __restrict__ C)
{
    __shared__ float As[16][132];   // [k][m], padded vs STS conflicts
    __shared__ float Bs[16][128];   // [k][n]

    const int tid = threadIdx.x;
    const int tx = tid & 15, ty = tid >> 4;
    const int m0 = blockIdx.y << 7, n0 = blockIdx.x << 7;

    const int arow = tid >> 2;          // 0..63
    const int akq  = (tid & 3) << 2;    // 0,4,8,12
    const int bkr  = tid >> 5;          // 0..7
    const int bcol = (tid & 31) << 2;   // 0..124

    float acc[8][8];
    #pragma unroll
    for (int i = 0; i < 8; i++)
        #pragma unroll
        for (int j = 0; j < 8; j++) acc[i][j] = 0.f;

    for (int k0 = 0; k0 < K_; k0 += 16) {
        float4 a0 = *(const float4*)(A + (size_t)(m0 + arow     ) * K_ + k0 + akq);
        float4 a1 = *(const float4*)(A + (size_t)(m0 + arow + 64) * K_ + k0 + akq);
        float4 b0 = *(const float4*)(W + (size_t)(k0 + bkr    ) * N_ + n0 + bcol);
        float4 b1 = *(const float4*)(W + (size_t)(k0 + bkr + 8) * N_ + n0 + bcol);
        __syncthreads();
        As[akq + 0][arow] = a0.x; As[akq + 1][arow] = a0.y;
        As[akq + 2][arow] = a0.z; As[akq + 3][arow] = a0.w;
        As[akq + 0][arow + 64] = a1.x; As[akq + 1][arow + 64] = a1.y;
        As[akq + 2][arow + 64] = a1.z; As[akq + 3][arow + 64] = a1.w;
        *(float4*)&Bs[bkr    ][bcol] = b0;
        *(float4*)&Bs[bkr + 8][bcol] = b1;
        __syncthreads();

        #pragma unroll
        for (int kk = 0; kk < 16; kk++) {
            float ar[8], br[8];
            *(float4*)&ar[0] = *(const float4*)&As[kk][ty * 8];
            *(float4*)&ar[4] = *(const float4*)&As[kk][ty * 8 + 4];
            *(float4*)&br[0] = *(const float4*)&Bs[kk][tx * 8];
            *(float4*)&br[4] = *(const float4*)&Bs[kk][tx * 8 + 4];
            #pragma unroll
            for (int i = 0; i < 8; i++)
                #pragma unroll
                for (int j = 0; j < 8; j++)
                    acc[i][j] = fmaf(ar[i], br[j], acc[i][j]);
        }
    }

    #pragma unroll
    for (int i = 0; i < 8; i++) {
        const int row = m0 + ty * 8 + i;
        #pragma unroll
        for (int j4 = 0; j4 < 8; j4 += 4) {
            float4 o;
            o.x = acc[i][j4 + 0] + bias[n0 + tx * 8 + j4 + 0];
            o.y = acc[i][j4 + 1] + bias[n0 + tx * 8 + j4 + 1];
            o.z = acc[i][j4 + 2] + bias[n0 + tx * 8 + j4 + 2];
            o.w = acc[i][j4 + 3] + bias[n0 + tx * 8 + j4 + 3];
            *(float4*)(C + (size_t)row * N_ + n0 + tx * 8 + j4) = o;
        }
    }
}

// ---------------------------------------------------------------------------
// Flash attention, fp32 SIMT. Grid: (T/64, H, B). 256 threads (16x16),
// 4x4 microtile. Online softmax; never materializes [T,T] scores.
// ---------------------------------------------------------------------------
#define SPITCH 68    // padded float stride for 64-wide smem tiles

__global__ __launch_bounds__(256) void flash_attn(const void* __restrict__ maskp)
{
    extern __shared__ float sm[];
    float* QsT = sm;                 // [d][r]  64 x SPITCH
    float* KsT = sm + 64 * SPITCH;   // [d][c]
    float* Vs  = sm + 2 * 64 * SPITCH; // [c][d]
    float* Ps  = sm + 3 * 64 * SPITCH; // [r][c]

    const int b  = blockIdx.z, h = blockIdx.y, qt = blockIdx.x;
    const int tid = threadIdx.x;
    const int tx = tid & 15, ty = tid >> 4;
    const float scale = 0.125f;  // D^-0.5

    const int is_byte = g_mask_is_byte;
    const unsigned char* mask_b = (const unsigned char*)maskp;
    const int*           mask_w = (const int*)maskp;

    // Load Q tile (64 rows x 64 d), transposed into QsT, scale folded in.
    #pragma unroll
    for (int e = 0; e < 4; e++) {
        int idx = tid + e * 256;
        int r  = idx >> 4;           // 0..63
        int d4 = (idx & 15) << 2;    // 0..60
        const float* qp = g_q + (size_t)((b * T_ + qt * 64 + r)) * N_ + h * D_ + d4;
        float4 qv = *(const float4*)qp;
        QsT[(d4 + 0) * SPITCH + r] = qv.x * scale;
        QsT[(d4 + 1) * SPITCH + r] = qv.y * scale;
        QsT[(d4 + 2) * SPITCH + r] = qv.z * scale;
        QsT[(d4 + 3) * SPITCH + r] = qv.w * scale;
    }

    float m_i[4], l_i[4], o[4][4];
    #pragma unroll
    for (int i = 0; i < 4; i++) {
        m_i[i] = -INFINITY; l_i[i] = 0.f;
        #pragma unroll
        for (int j = 0; j < 4; j++) o[i][j] = 0.f;
    }

    for (int kt = 0; kt < T_ / 64; kt++) {
        // Load K (transposed) and V tiles
        #pragma unroll
        for (int e = 0; e < 4; e++) {
            int idx = tid + e * 256;
            int r  = idx >> 4;
            int d4 = (idx & 15) << 2;
            size_t base = (size_t)((b * T_ + kt * 64 + r)) * N_ + h * D_ + d4;
            float4 kv = *(const float4*)(g_k + base);
            KsT[(d4 + 0) * SPITCH + r] = kv.x;
            KsT[(d4 + 1) * SPITCH + r] = kv.y;
            KsT[(d4 + 2) * SPITCH + r] = kv.z;
            KsT[(d4 + 3) * SPITCH + r] = kv.w;
            float4 vv = *(const float4*)(g_v + base);
            *(float4*)&Vs[r * SPITCH + d4] = vv;
        }
        __syncthreads();

        // S = Q @ K^T (scaled)
        float s[4][4];
        #pragma unroll
        for (int i = 0; i < 4; i++)
            #pragma unroll
            for (int j = 0; j < 4; j++) s[i][j] = 0.f;

        #pragma unroll 16
        for (int d = 0; d < 64; d++) {
            float4 aq = *(const float4*)&QsT[d * SPITCH + ty * 4];
            float4 bk = *(const float4*)&KsT[d * SPITCH + tx * 4];
            float ar[4] = {aq.x, aq.y, aq.z, aq.w};
            float br[4] = {bk.x, bk.y, bk.z, bk.w};
            #pragma unroll
            for (int i = 0; i < 4; i++)
                #pragma unroll
                for (int j = 0; j < 4; j++)
                    s[i][j] = fmaf(ar[i], br[j], s[i][j]);
        }

        // Mask (exactly like ref: masked -> -FLT_MAX, pre-softmax)
        const int trow0 = qt * 64 + ty * 4;
        const int kc0   = kt * 64 + tx * 4;
        #pragma unroll
        for (int i = 0; i < 4; i++) {
            size_t midx = ((size_t)b * T_ + trow0 + i) * T_ + kc0;
            int mv[4];
            if (is_byte) {
                uchar4 u = *(const uchar4*)(mask_b + midx);
                mv[0] = u.x; mv[1] = u.y; mv[2] = u.z; mv[3] = u.w;
            } else {
                int4 u = *(const int4*)(mask_w + midx);
                mv[0] = u.x; mv[1] = u.y; mv[2] = u.z; mv[3] = u.w;
            }
            #pragma unroll
            for (int j = 0; j < 4; j++)
                if (mv[j] == 0) s[i][j] = -3.402823466e38f;
        }

        // Online softmax update + write P
        #pragma unroll
        for (int i = 0; i < 4; i++) {
            float mx = fmaxf(fmaxf(s[i][0], s[i][1]), fmaxf(s[i][2], s[i][3]));
            #pragma unroll
            for (int off = 1; off < 16; off <<= 1)
                mx = fmaxf(mx, __shfl_xor_sync(0xffffffffu, mx, off));
            float mnew = fmaxf(m_i[i], mx);
            float corr = __expf(m_i[i] - mnew);   // exp(-inf)=0 handles init
            float p[4], rs = 0.f;
            #pragma unroll
            for (int j = 0; j < 4; j++) { p[j] = __expf(s[i][j] - mnew); rs += p[j]; }
            #pragma unroll
            for (int off = 1; off < 16; off <<= 1)
                rs += __shfl_xor_sync(0xffffffffu, rs, off);
            l_i[i] = l_i[i] * corr + rs;
            m_i[i] = mnew;
            #pragma unroll
            for (int j = 0; j < 4; j++) o[i][j] *= corr;
            *(float4*)&Ps[(ty * 4 + i) * SPITCH + tx * 4] =
                make_float4(p[0], p[1], p[2], p[3]);
        }
        __syncthreads();

        // O += P @ V
        #pragma unroll 16
        for (int kc = 0; kc < 64; kc++) {
            float a0 = Ps[(ty * 4 + 0) * SPITCH + kc];
            float a1 = Ps[(ty * 4 + 1) * SPITCH + kc];
            float a2 = Ps[(ty * 4 + 2) * SPITCH + kc];
            float a3 = Ps[(ty * 4 + 3) * SPITCH + kc];
            float4 vv = *(const float4*)&Vs[kc * SPITCH + tx * 4];
            float vr[4] = {vv.x, vv.y, vv.z, vv.w};
            #pragma unroll
            for (int j = 0; j < 4; j++) {
                o[0][j] = fmaf(a0, vr[j], o[0][j]);
                o[1][j] = fmaf(a1, vr[j], o[1][j]);
                o[2][j] = fmaf(a2, vr[j], o[2][j]);
                o[3][j] = fmaf(a3, vr[j], o[3][j]);
            }
        }
        __syncthreads();
    }

    // Epilogue: normalize and write z[b,t,h,d]
    #pragma unroll
    for (int i = 0; i < 4; i++) {
        float inv = 1.f / l_i[i];
        int row = qt * 64 + ty * 4 + i;
        float4 ov = make_float4(o[i][0] * inv, o[i][1] * inv,
                                o[i][2] * inv, o[i][3] * inv);
        *(float4*)(g_z + (size_t)(b * T_ + row) * N_ + h * D_ + tx * 4) = ov;
    }
}

// ---------------------------------------------------------------------------
extern "C" void kernel_launch(void* const* d_in, const int* in_sizes, int n_in,
                              void* d_out, int out_size)
{
    const float* embed = (const float*)d_in[0];
    const void*  mask  = d_in[1];
    const float* Wq = (const float*)d_in[2]; const float* bq = (const float*)d_in[3];
    const float* Wk = (const float*)d_in[4]; const float* bk = (const float*)d_in[5];
    const float* Wv = (const float*)d_in[6]; const float* bv = (const float*)d_in[7];
    const float* Wz = (const float*)d_in[8]; const float* bz = (const float*)d_in[9];
    float* out = (float*)d_out;

    float *q, *k, *v, *z;
    cudaGetSymbolAddress((void**)&q, g_q);
    cudaGetSymbolAddress((void**)&k, g_k);
    cudaGetSymbolAddress((void**)&v, g_v);
    cudaGetSymbolAddress((void**)&z, g_z);

    detect_mask_kernel<<<1, 256>>>((const unsigned int*)mask);

    dim3 gg(N_ / 128, M_ / 128);
    sgemm_bias<<<gg, 256>>>(embed, Wq, bq, q);
    sgemm_bias<<<gg, 256>>>(embed, Wk, bk, k);
    sgemm_bias<<<gg, 256>>>(embed, Wv, bv, v);

    size_t smem = 4 * 64 * SPITCH * sizeof(float);  // ~69.6 KB
    cudaFuncSetAttribute(flash_attn, cudaFuncAttributeMaxDynamicSharedMemorySize,
                         (int)smem);
    flash_attn<<<dim3(T_ / 64, H_, B_), 256, smem>>>(mask);

    sgemm_bias<<<gg, 256>>>(z, Wz, bz, out);
}

// round 6
// speedup vs baseline: 1.6830x; 1.6830x over previous
#include <cuda_runtime.h>
#include <math.h>

#define B_ 2
#define T_ 2048
#define E_ 1024
#define H_ 16
#define D_ 64
#define M_ (B_*T_)
#define N_ 1024
#define K_ 1024

// Scratch (allocation-free rule: __device__ globals)
__device__ float g_q[M_*N_];
__device__ float g_k[M_*N_];
__device__ float g_v[M_*N_];
__device__ float g_z[M_*N_];
__device__ int   g_mask_is_byte;

// ---------------------------------------------------------------------------
// Helpers: TF32 convert + m16n8k8 TF32 MMA
// ---------------------------------------------------------------------------
__device__ __forceinline__ unsigned f2tf(float x) {
    unsigned u;
    asm("cvt.rna.tf32.f32 %0, %1;" : "=r"(u) : "f"(x));
    return u;
}

__device__ __forceinline__ void mma_tf32(float c[4],
    unsigned a0, unsigned a1, unsigned a2, unsigned a3,
    unsigned b0, unsigned b1)
{
    asm volatile(
        "mma.sync.aligned.m16n8k8.row.col.f32.tf32.tf32.f32 "
        "{%0,%1,%2,%3}, {%4,%5,%6,%7}, {%8,%9}, {%0,%1,%2,%3};\n"
        : "+f"(c[0]), "+f"(c[1]), "+f"(c[2]), "+f"(c[3])
        : "r"(a0), "r"(a1), "r"(a2), "r"(a3), "r"(b0), "r"(b1));
}

// ---------------------------------------------------------------------------
// Mask dtype detection (1-byte vs 4-byte bool storage)
// ---------------------------------------------------------------------------
__global__ void detect_mask_kernel(const unsigned int* __restrict__ w) {
    __shared__ int bad;
    if (threadIdx.x == 0) bad = 0;
    __syncthreads();
    int local = 0;
    for (int i = threadIdx.x; i < 4096; i += blockDim.x) {
        unsigned int x = w[i];
        if (x != 0u && x != 1u && x != 0x3F800000u) local = 1;
    }
    if (local) atomicOr(&bad, 1);
    __syncthreads();
    if (threadIdx.x == 0) g_mask_is_byte = bad;
}

// ---------------------------------------------------------------------------
// TF32 tensor-core GEMM: C[M,N] = A[M,K] @ W[K,N] + bias
// 128x128 block, BK=16, 8 warps (2x4), warp tile 64x32 (4x4 m16n8k8).
// ---------------------------------------------------------------------------
#define AP 20    // As pitch (words): 20 mod 32 -> conflict-free A-frag loads
#define BP 136   // Bs pitch (words): 136 mod 32 = 8 -> conflict-free B-frag

__global__ __launch_bounds__(256) void gemm_tf32(
    const float* __restrict__ A, const float* __restrict__ W,
    const float* __restrict__ bias, float* __restrict__ C)
{
    __shared__ unsigned As[128 * AP];   // [m][k] tf32
    __shared__ unsigned Bs[16 * BP];    // [k][n] tf32

    const int tid  = threadIdx.x;
    const int wid  = tid >> 5, lane = tid & 31;
    const int g    = lane >> 2, t = lane & 3;
    const int wm   = wid & 1,  wn = wid >> 1;     // warp grid 2 x 4
    const int m0   = blockIdx.y << 7, n0 = blockIdx.x << 7;

    const int ar = tid >> 2;          // A load row 0..63 (and +64)
    const int ak = (tid & 3) << 2;    // A load k-offset 0,4,8,12
    const int bk = tid >> 5;          // B load k 0..7 (and +8)
    const int bn = (tid & 31) << 2;   // B load n-offset 0..124

    const float* Ap0 = A + (size_t)(m0 + ar) * K_ + ak;
    const float* Ap1 = Ap0 + (size_t)64 * K_;
    const float* Wp0 = W + (size_t)bk * N_ + n0 + bn;
    const float* Wp1 = Wp0 + (size_t)8 * N_;

    float acc[4][4][4];
    #pragma unroll
    for (int mi = 0; mi < 4; mi++)
        #pragma unroll
        for (int ni = 0; ni < 4; ni++)
            #pragma unroll
            for (int r = 0; r < 4; r++) acc[mi][ni][r] = 0.f;

    float4 a0v = *(const float4*)Ap0;
    float4 a1v = *(const float4*)Ap1;
    float4 b0v = *(const float4*)Wp0;
    float4 b1v = *(const float4*)Wp1;

    for (int k0 = 0; k0 < K_; k0 += 16) {
        __syncthreads();
        As[ar * AP + ak + 0] = f2tf(a0v.x); As[ar * AP + ak + 1] = f2tf(a0v.y);
        As[ar * AP + ak + 2] = f2tf(a0v.z); As[ar * AP + ak + 3] = f2tf(a0v.w);
        As[(ar + 64) * AP + ak + 0] = f2tf(a1v.x);
        As[(ar + 64) * AP + ak + 1] = f2tf(a1v.y);
        As[(ar + 64) * AP + ak + 2] = f2tf(a1v.z);
        As[(ar + 64) * AP + ak + 3] = f2tf(a1v.w);
        Bs[bk * BP + bn + 0] = f2tf(b0v.x); Bs[bk * BP + bn + 1] = f2tf(b0v.y);
        Bs[bk * BP + bn + 2] = f2tf(b0v.z); Bs[bk * BP + bn + 3] = f2tf(b0v.w);
        Bs[(bk + 8) * BP + bn + 0] = f2tf(b1v.x);
        Bs[(bk + 8) * BP + bn + 1] = f2tf(b1v.y);
        Bs[(bk + 8) * BP + bn + 2] = f2tf(b1v.z);
        Bs[(bk + 8) * BP + bn + 3] = f2tf(b1v.w);
        __syncthreads();

        if (k0 + 16 < K_) {   // prefetch next tile during compute
            a0v = *(const float4*)(Ap0 + k0 + 16);
            a1v = *(const float4*)(Ap1 + k0 + 16);
            b0v = *(const float4*)(Wp0 + (size_t)(k0 + 16) * N_);
            b1v = *(const float4*)(Wp1 + (size_t)(k0 + 16) * N_);
        }

        #pragma unroll
        for (int kk = 0; kk < 16; kk += 8) {
            unsigned af[4][4], bf[4][2];
            #pragma unroll
            for (int mi = 0; mi < 4; mi++) {
                int row = wm * 64 + mi * 16 + g;
                af[mi][0] = As[row * AP + kk + t];
                af[mi][1] = As[(row + 8) * AP + kk + t];
                af[mi][2] = As[row * AP + kk + t + 4];
                af[mi][3] = As[(row + 8) * AP + kk + t + 4];
            }
            #pragma unroll
            for (int ni = 0; ni < 4; ni++) {
                int col = wn * 32 + ni * 8 + g;
                bf[ni][0] = Bs[(kk + t) * BP + col];
                bf[ni][1] = Bs[(kk + t + 4) * BP + col];
            }
            #pragma unroll
            for (int mi = 0; mi < 4; mi++)
                #pragma unroll
                for (int ni = 0; ni < 4; ni++)
                    mma_tf32(acc[mi][ni], af[mi][0], af[mi][1], af[mi][2],
                             af[mi][3], bf[ni][0], bf[ni][1]);
        }
    }

    // Epilogue: C-fragment rows g/g+8, cols 2t/2t+1
    #pragma unroll
    for (int mi = 0; mi < 4; mi++) {
        #pragma unroll
        for (int ni = 0; ni < 4; ni++) {
            int row = m0 + wm * 64 + mi * 16 + g;
            int col = n0 + wn * 32 + ni * 8 + 2 * t;
            float bz0 = bias[col], bz1 = bias[col + 1];
            float2 w0 = make_float2(acc[mi][ni][0] + bz0, acc[mi][ni][1] + bz1);
            float2 w1 = make_float2(acc[mi][ni][2] + bz0, acc[mi][ni][3] + bz1);
            *(float2*)(C + (size_t)row * N_ + col) = w0;
            *(float2*)(C + (size_t)(row + 8) * N_ + col) = w1;
        }
    }
}

// ---------------------------------------------------------------------------
// TF32 tensor-core flash attention. Grid (T/128, H, B), 256 thr (8 warps),
// each warp owns 16 q-rows. BQ=128, BC=64. Softmax math stays fp32.
// ---------------------------------------------------------------------------
#define QP 68   // pitch for Qs/Ks/Ps: A-style frag loads conflict-free
#define VP 72   // pitch for Vs: 72 mod 32 = 8 -> B-style frag conflict-free

__global__ __launch_bounds__(256) void flash_attn_tc(const void* __restrict__ maskp)
{
    extern __shared__ unsigned smu[];
    unsigned* Qs = smu;                   // [128][QP]
    unsigned* Ks = Qs + 128 * QP;         // [64][QP]
    unsigned* Vs = Ks + 64 * QP;          // [64][VP]
    unsigned* Ps = Vs + 64 * VP;          // [128][QP]

    const int b = blockIdx.z, h = blockIdx.y, qt = blockIdx.x;
    const int tid = threadIdx.x;
    const int wid = tid >> 5, lane = tid & 31;
    const int g = lane >> 2, t = lane & 3;
    const int qrow = wid * 16;

    const int is_byte = g_mask_is_byte;
    const unsigned char* mask_b = (const unsigned char*)maskp;
    const int*           mask_w = (const int*)maskp;

    // Load Q tile (128 x 64), scale folded, cvt to tf32
    #pragma unroll
    for (int e = 0; e < 8; e++) {
        int idx = tid + e * 256;
        int r = idx >> 4, d4 = (idx & 15) << 2;
        float4 qv = *(const float4*)(g_q + (size_t)(b * T_ + qt * 128 + r) * N_ + h * D_ + d4);
        Qs[r * QP + d4 + 0] = f2tf(qv.x * 0.125f);
        Qs[r * QP + d4 + 1] = f2tf(qv.y * 0.125f);
        Qs[r * QP + d4 + 2] = f2tf(qv.z * 0.125f);
        Qs[r * QP + d4 + 3] = f2tf(qv.w * 0.125f);
    }

    float m_i[2] = {-INFINITY, -INFINITY};
    float l_i[2] = {0.f, 0.f};
    float o[8][4];
    #pragma unroll
    for (int nt = 0; nt < 8; nt++)
        #pragma unroll
        for (int r = 0; r < 4; r++) o[nt][r] = 0.f;

    for (int kt = 0; kt < T_ / 64; kt++) {
        __syncthreads();
        #pragma unroll
        for (int e = 0; e < 4; e++) {
            int idx = tid + e * 256;
            int r = idx >> 4, d4 = (idx & 15) << 2;
            size_t base = (size_t)(b * T_ + kt * 64 + r) * N_ + h * D_ + d4;
            float4 kv = *(const float4*)(g_k + base);
            Ks[r * QP + d4 + 0] = f2tf(kv.x); Ks[r * QP + d4 + 1] = f2tf(kv.y);
            Ks[r * QP + d4 + 2] = f2tf(kv.z); Ks[r * QP + d4 + 3] = f2tf(kv.w);
            float4 vv = *(const float4*)(g_v + base);
            Vs[r * VP + d4 + 0] = f2tf(vv.x); Vs[r * VP + d4 + 1] = f2tf(vv.y);
            Vs[r * VP + d4 + 2] = f2tf(vv.z); Vs[r * VP + d4 + 3] = f2tf(vv.w);
        }
        __syncthreads();

        // ---- S = Q @ K^T  (warp: 16 x 64) ----
        float s[8][4];
        #pragma unroll
        for (int nt = 0; nt < 8; nt++)
            #pragma unroll
            for (int r = 0; r < 4; r++) s[nt][r] = 0.f;

        #pragma unroll
        for (int kk = 0; kk < 8; kk++) {
            unsigned a0 = Qs[(qrow + g) * QP + kk * 8 + t];
            unsigned a1 = Qs[(qrow + g + 8) * QP + kk * 8 + t];
            unsigned a2 = Qs[(qrow + g) * QP + kk * 8 + t + 4];
            unsigned a3 = Qs[(qrow + g + 8) * QP + kk * 8 + t + 4];
            #pragma unroll
            for (int nt = 0; nt < 8; nt++) {
                unsigned b0 = Ks[(nt * 8 + g) * QP + kk * 8 + t];
                unsigned b1 = Ks[(nt * 8 + g) * QP + kk * 8 + t + 4];
                mma_tf32(s[nt], a0, a1, a2, a3, b0, b1);
            }
        }

        // ---- mask + online softmax (fp32), write P (tf32) ----
        #pragma unroll
        for (int half = 0; half < 2; half++) {
            const int r0 = half * 2;                 // frag regs r0, r0+1
            int rowg = qt * 128 + qrow + g + half * 8;
            size_t mbase = ((size_t)b * T_ + rowg) * T_ + kt * 64;

            #pragma unroll
            for (int nt = 0; nt < 8; nt++) {
                int col = nt * 8 + 2 * t;
                int mv0, mv1;
                if (is_byte) {
                    uchar2 u = *(const uchar2*)(mask_b + mbase + col);
                    mv0 = u.x; mv1 = u.y;
                } else {
                    int2 u = *(const int2*)(mask_w + mbase + col);
                    mv0 = u.x; mv1 = u.y;
                }
                if (mv0 == 0) s[nt][r0 + 0] = -3.402823466e38f;
                if (mv1 == 0) s[nt][r0 + 1] = -3.402823466e38f;
            }

            float mx = -INFINITY;
            #pragma unroll
            for (int nt = 0; nt < 8; nt++)
                mx = fmaxf(mx, fmaxf(s[nt][r0], s[nt][r0 + 1]));
            mx = fmaxf(mx, __shfl_xor_sync(0xffffffffu, mx, 1));
            mx = fmaxf(mx, __shfl_xor_sync(0xffffffffu, mx, 2));

            float mnew = fmaxf(m_i[half], mx);
            float corr = __expf(m_i[half] - mnew);
            float rs = 0.f;
            #pragma unroll
            for (int nt = 0; nt < 8; nt++) {
                float p0 = __expf(s[nt][r0] - mnew);
                float p1 = __expf(s[nt][r0 + 1] - mnew);
                rs += p0 + p1;
                s[nt][r0] = p0; s[nt][r0 + 1] = p1;
            }
            rs += __shfl_xor_sync(0xffffffffu, rs, 1);
            rs += __shfl_xor_sync(0xffffffffu, rs, 2);
            l_i[half] = l_i[half] * corr + rs;
            m_i[half] = mnew;
            #pragma unroll
            for (int nt = 0; nt < 8; nt++) {
                o[nt][r0] *= corr; o[nt][r0 + 1] *= corr;
                int prow = (qrow + g + half * 8) * QP + nt * 8 + 2 * t;
                Ps[prow]     = f2tf(s[nt][r0]);
                Ps[prow + 1] = f2tf(s[nt][r0 + 1]);
            }
        }
        __syncwarp();

        // ---- O += P @ V  (warp: 16 x 64, k = 64) ----
        #pragma unroll
        for (int kk = 0; kk < 8; kk++) {
            unsigned a0 = Ps[(qrow + g) * QP + kk * 8 + t];
            unsigned a1 = Ps[(qrow + g + 8) * QP + kk * 8 + t];
            unsigned a2 = Ps[(qrow + g) * QP + kk * 8 + t + 4];
            unsigned a3 = Ps[(qrow + g + 8) * QP + kk * 8 + t + 4];
            #pragma unroll
            for (int nt = 0; nt < 8; nt++) {
                unsigned b0 = Vs[(kk * 8 + t) * VP + nt * 8 + g];
                unsigned b1 = Vs[(kk * 8 + t + 4) * VP + nt * 8 + g];
                mma_tf32(o[nt], a0, a1, a2, a3, b0, b1);
            }
        }
    }

    // Epilogue: normalize, write z[b,t,h,d]
    #pragma unroll
    for (int half = 0; half < 2; half++) {
        float inv = 1.f / l_i[half];
        int rowg = qt * 128 + qrow + g + half * 8;
        #pragma unroll
        for (int nt = 0; nt < 8; nt++) {
            float2 ov = make_float2(o[nt][half * 2] * inv,
                                    o[nt][half * 2 + 1] * inv);
            *(float2*)(g_z + (size_t)(b * T_ + rowg) * N_ + h * D_ + nt * 8 + 2 * t) = ov;
        }
    }
}

// ---------------------------------------------------------------------------
extern "C" void kernel_launch(void* const* d_in, const int* in_sizes, int n_in,
                              void* d_out, int out_size)
{
    const float* embed = (const float*)d_in[0];
    const void*  mask  = d_in[1];
    const float* Wq = (const float*)d_in[2]; const float* bq = (const float*)d_in[3];
    const float* Wk = (const float*)d_in[4]; const float* bk = (const float*)d_in[5];
    const float* Wv = (const float*)d_in[6]; const float* bv = (const float*)d_in[7];
    const float* Wz = (const float*)d_in[8]; const float* bz = (const float*)d_in[9];
    float* out = (float*)d_out;

    float *q, *k, *v, *z;
    cudaGetSymbolAddress((void**)&q, g_q);
    cudaGetSymbolAddress((void**)&k, g_k);
    cudaGetSymbolAddress((void**)&v, g_v);
    cudaGetSymbolAddress((void**)&z, g_z);

    detect_mask_kernel<<<1, 256>>>((const unsigned int*)mask);

    dim3 gg(N_ / 128, M_ / 128);
    gemm_tf32<<<gg, 256>>>(embed, Wq, bq, q);
    gemm_tf32<<<gg, 256>>>(embed, Wk, bk, k);
    gemm_tf32<<<gg, 256>>>(embed, Wv, bv, v);

    size_t smem = (size_t)(128 * QP + 64 * QP + 64 * VP + 128 * QP) * 4;
    cudaFuncSetAttribute(flash_attn_tc,
                         cudaFuncAttributeMaxDynamicSharedMemorySize, (int)smem);
    flash_attn_tc<<<dim3(T_ / 128, H_, B_), 256, smem>>>(mask);

    gemm_tf32<<<gg, 256>>>(z, Wz, bz, out);
}

// round 13
// speedup vs baseline: 2.3450x; 1.3934x over previous
#include <cuda_runtime.h>
#include <math.h>
#include <stdint.h>

#define B_ 2
#define T_ 2048
#define E_ 1024
#define H_ 16
#define D_ 64
#define M_ (B_*T_)
#define N_ 1024
#define K_ 1024

// Scratch (allocation-free rule: __device__ globals)
__device__ float g_q[M_*N_];
__device__ float g_k[M_*N_];
__device__ float g_v[M_*N_];
__device__ float g_z[M_*N_];
__device__ float g_wt[4ull * 1024 * 1024];   // K-major transposed weights
__device__ int   g_mask_is_byte;

// ---------------------------------------------------------------------------
// Helpers
// ---------------------------------------------------------------------------
__device__ __forceinline__ unsigned f2tf(float x) {
    unsigned u;
    asm("cvt.rna.tf32.f32 %0, %1;" : "=r"(u) : "f"(x));
    return u;
}

__device__ __forceinline__ void mma_tf32(float c[4],
    unsigned a0, unsigned a1, unsigned a2, unsigned a3,
    unsigned b0, unsigned b1)
{
    asm volatile(
        "mma.sync.aligned.m16n8k8.row.col.f32.tf32.tf32.f32 "
        "{%0,%1,%2,%3}, {%4,%5,%6,%7}, {%8,%9}, {%0,%1,%2,%3};\n"
        : "+f"(c[0]), "+f"(c[1]), "+f"(c[2]), "+f"(c[3])
        : "r"(a0), "r"(a1), "r"(a2), "r"(a3), "r"(b0), "r"(b1));
}

// k-permutation within an 8-group: order [0,4,1,5,2,6,3,7] so that
// (k=t, k=t+4) land at adjacent positions (2t, 2t+1) -> LDS.64 frag loads.
__device__ __forceinline__ int pos8(int c) {
    return (c & 4) ? (((c & 3) << 1) | 1) : (c << 1);
}

// ---------------------------------------------------------------------------
// Mask dtype detection (1-byte vs 4-byte bool storage)
// ---------------------------------------------------------------------------
__global__ void detect_mask_kernel(const unsigned int* __restrict__ w) {
    __shared__ int bad;
    if (threadIdx.x == 0) bad = 0;
    __syncthreads();
    int local = 0;
    for (int i = threadIdx.x; i < 4096; i += blockDim.x) {
        unsigned int x = w[i];
        if (x != 0u && x != 1u && x != 0x3F800000u) local = 1;
    }
    if (local) atomicOr(&bad, 1);
    __syncthreads();
    if (threadIdx.x == 0) g_mask_is_byte = bad;
}

// ---------------------------------------------------------------------------
// Batched 1024x1024 transpose: out[z][n][k] = W_z[k][n]  (4 weight matrices)
// ---------------------------------------------------------------------------
__global__ void transpose4(const float* __restrict__ w0, const float* __restrict__ w1,
                           const float* __restrict__ w2, const float* __restrict__ w3,
                           float* __restrict__ out)
{
    __shared__ float t[32][33];
    const float* src = (blockIdx.z == 0) ? w0 : (blockIdx.z == 1) ? w1
                     : (blockIdx.z == 2) ? w2 : w3;
    float* dst = out + (size_t)blockIdx.z * 1024 * 1024;
    int x = blockIdx.x * 32 + threadIdx.x;
    int y = blockIdx.y * 32 + threadIdx.y;
    #pragma unroll
    for (int j = 0; j < 32; j += 8)
        t[threadIdx.y + j][threadIdx.x] = src[(size_t)(y + j) * 1024 + x];
    __syncthreads();
    x = blockIdx.y * 32 + threadIdx.x;
    y = blockIdx.x * 32 + threadIdx.y;
    #pragma unroll
    for (int j = 0; j < 32; j += 8)
        dst[(size_t)(y + j) * 1024 + x] = t[threadIdx.x][threadIdx.y + j];
}

// ---------------------------------------------------------------------------
// TF32 mma.sync GEMM body: C[M,N] = A[M,K] @ BT^T + bias (BT K-major [N,K]).
// 128x128 tile, BK=16, double-buffered smem (1 bar/chunk), k-permuted layout
// with pitch 24 (== 8 mod 32 -> conflict-free LDS.64 fragment loads).
// ---------------------------------------------------------------------------
#define GP 24               // smem pitch in words (16 data + 8 pad)
#define GBUF (128 * GP)     // words per buffer per matrix

__device__ __forceinline__ void gemm_body(
    const float* __restrict__ A, const float* __restrict__ BT,
    const float* __restrict__ bias, float* __restrict__ C,
    unsigned* __restrict__ As, unsigned* __restrict__ Bs)
{
    const int tid = threadIdx.x, wid = tid >> 5, lane = tid & 31;
    const int g = lane >> 2, t = lane & 3;
    const int wm = wid & 1, wn = wid >> 1;           // warp grid 2 x 4
    const int m0 = blockIdx.y << 7, n0 = blockIdx.x << 7;

    const int r0 = tid >> 2;                         // load row 0..63 (+64)
    const int kq = (tid & 3) << 2;                   // k-offset 0,4,8,12
    const int pb = ((kq >> 3) << 3) | ((kq & 4) >> 2);  // perm base (+2*i)

    const float* Ap0 = A  + (size_t)(m0 + r0) * K_ + kq;
    const float* Ap1 = Ap0 + (size_t)64 * K_;
    const float* Bp0 = BT + (size_t)(n0 + r0) * K_ + kq;
    const float* Bp1 = Bp0 + (size_t)64 * K_;

    float acc[4][4][4];
    #pragma unroll
    for (int mi = 0; mi < 4; mi++)
        #pragma unroll
        for (int ni = 0; ni < 4; ni++)
            #pragma unroll
            for (int r = 0; r < 4; r++) acc[mi][ni][r] = 0.f;

    float4 av0 = *(const float4*)Ap0, av1 = *(const float4*)Ap1;
    float4 bv0 = *(const float4*)Bp0, bv1 = *(const float4*)Bp1;

    for (int c = 0; c < 64; ++c) {
        unsigned* ab = As + (c & 1) * GBUF;
        unsigned* bb = Bs + (c & 1) * GBUF;
        unsigned* p;
        p = ab + r0 * GP + pb;
        p[0] = f2tf(av0.x); p[2] = f2tf(av0.y); p[4] = f2tf(av0.z); p[6] = f2tf(av0.w);
        p = ab + (r0 + 64) * GP + pb;
        p[0] = f2tf(av1.x); p[2] = f2tf(av1.y); p[4] = f2tf(av1.z); p[6] = f2tf(av1.w);
        p = bb + r0 * GP + pb;
        p[0] = f2tf(bv0.x); p[2] = f2tf(bv0.y); p[4] = f2tf(bv0.z); p[6] = f2tf(bv0.w);
        p = bb + (r0 + 64) * GP + pb;
        p[0] = f2tf(bv1.x); p[2] = f2tf(bv1.y); p[4] = f2tf(bv1.z); p[6] = f2tf(bv1.w);
        __syncthreads();

        if (c < 63) {   // prefetch next chunk while computing this one
            int k0 = (c + 1) << 4;
            av0 = *(const float4*)(Ap0 + k0); av1 = *(const float4*)(Ap1 + k0);
            bv0 = *(const float4*)(Bp0 + k0); bv1 = *(const float4*)(Bp1 + k0);
        }

        #pragma unroll
        for (int kk = 0; kk < 16; kk += 8) {
            uint2 alo[4], ahi[4], bfr[4];
            #pragma unroll
            for (int mi = 0; mi < 4; mi++) {
                int row = wm * 64 + mi * 16 + g;
                alo[mi] = *(const uint2*)(ab + row * GP + kk + 2 * t);
                ahi[mi] = *(const uint2*)(ab + (row + 8) * GP + kk + 2 * t);
            }
            #pragma unroll
            for (int ni = 0; ni < 4; ni++) {
                int col = wn * 32 + ni * 8 + g;
                bfr[ni] = *(const uint2*)(bb + col * GP + kk + 2 * t);
            }
            #pragma unroll
            for (int mi = 0; mi < 4; mi++)
                #pragma unroll
                for (int ni = 0; ni < 4; ni++)
                    mma_tf32(acc[mi][ni], alo[mi].x, ahi[mi].x, alo[mi].y,
                             ahi[mi].y, bfr[ni].x, bfr[ni].y);
        }
    }

    #pragma unroll
    for (int mi = 0; mi < 4; mi++) {
        #pragma unroll
        for (int ni = 0; ni < 4; ni++) {
            int row = m0 + wm * 64 + mi * 16 + g;
            int col = n0 + wn * 32 + ni * 8 + 2 * t;
            float bz0 = bias[col], bz1 = bias[col + 1];
            float2 w0 = make_float2(acc[mi][ni][0] + bz0, acc[mi][ni][1] + bz1);
            float2 w1 = make_float2(acc[mi][ni][2] + bz0, acc[mi][ni][3] + bz1);
            *(float2*)(C + (size_t)row * N_ + col) = w0;
            *(float2*)(C + (size_t)(row + 8) * N_ + col) = w1;
        }
    }
}

#define GEMM_SMEM (4 * GBUF * 4)   // 2 buffers x (A+B) x 4B = 49152 B

__global__ __launch_bounds__(256, 2) void gemm_qkv(
    const float* __restrict__ A, const float* __restrict__ WT,
    const float* __restrict__ bq, const float* __restrict__ bk,
    const float* __restrict__ bv,
    float* __restrict__ q, float* __restrict__ k, float* __restrict__ v)
{
    extern __shared__ unsigned gsm[];
    const int z = blockIdx.z;
    const float* BT = WT + (size_t)z * 1024 * 1024;
    const float* bias = (z == 0) ? bq : (z == 1) ? bk : bv;
    float* C = (z == 0) ? q : (z == 1) ? k : v;
    gemm_body(A, BT, bias, C, gsm, gsm + 2 * GBUF);
}

__global__ __launch_bounds__(256, 2) void gemm_one(
    const float* __restrict__ A, const float* __restrict__ BT,
    const float* __restrict__ bias, float* __restrict__ C)
{
    extern __shared__ unsigned gsm[];
    gemm_body(A, BT, bias, C, gsm, gsm + 2 * GBUF);
}

// ---------------------------------------------------------------------------
// TF32 mma.sync flash attention, k-permuted LDS.64 fragment feeds.
// Grid (T/128, H, B), 256 thr (8 warps x 16 q-rows). BQ=128, BC=64.
// Qs/Ks/Ps: pitch 72 (== 8 mod 32), k-permuted. Vs: pitch 72, plain layout.
// ---------------------------------------------------------------------------
#define FP 72

__global__ __launch_bounds__(256) void flash_attn_tc(const void* __restrict__ maskp)
{
    extern __shared__ unsigned smu[];
    unsigned* Qs = smu;                   // [128][FP] permuted d
    unsigned* Ks = Qs + 128 * FP;         // [64][FP]  permuted d
    unsigned* Vs = Ks + 64 * FP;          // [64][FP]  plain [c][d]
    unsigned* Ps = Vs + 64 * FP;          // [128][FP] permuted c

    const int b = blockIdx.z, h = blockIdx.y, qt = blockIdx.x;
    const int tid = threadIdx.x;
    const int wid = tid >> 5, lane = tid & 31;
    const int g = lane >> 2, t = lane & 3;
    const int qrow = wid * 16;

    const int is_byte = g_mask_is_byte;
    const unsigned char* mask_b = (const unsigned char*)maskp;
    const int*           mask_w = (const int*)maskp;

    // Load Q tile (128 x 64), scale folded, permuted store
    #pragma unroll
    for (int e = 0; e < 8; e++) {
        int idx = tid + e * 256;
        int r = idx >> 4, d4 = (idx & 15) << 2;
        int pbq = ((d4 >> 3) << 3) | ((d4 & 4) >> 2);
        float4 qv = *(const float4*)(g_q + (size_t)(b * T_ + qt * 128 + r) * N_ + h * D_ + d4);
        unsigned* p = Qs + r * FP + pbq;
        p[0] = f2tf(qv.x * 0.125f); p[2] = f2tf(qv.y * 0.125f);
        p[4] = f2tf(qv.z * 0.125f); p[6] = f2tf(qv.w * 0.125f);
    }

    float m_i[2] = {-INFINITY, -INFINITY};
    float l_i[2] = {0.f, 0.f};
    float o[8][4];
    #pragma unroll
    for (int nt = 0; nt < 8; nt++)
        #pragma unroll
        for (int r = 0; r < 4; r++) o[nt][r] = 0.f;

    for (int kt = 0; kt < T_ / 64; kt++) {
        __syncthreads();
        #pragma unroll
        for (int e = 0; e < 4; e++) {
            int idx = tid + e * 256;
            int r = idx >> 4, d4 = (idx & 15) << 2;
            int pbk = ((d4 >> 3) << 3) | ((d4 & 4) >> 2);
            size_t base = (size_t)(b * T_ + kt * 64 + r) * N_ + h * D_ + d4;
            float4 kv = *(const float4*)(g_k + base);
            unsigned* p = Ks + r * FP + pbk;
            p[0] = f2tf(kv.x); p[2] = f2tf(kv.y); p[4] = f2tf(kv.z); p[6] = f2tf(kv.w);
            float4 vv = *(const float4*)(g_v + base);
            uint4 v4 = make_uint4(f2tf(vv.x), f2tf(vv.y), f2tf(vv.z), f2tf(vv.w));
            *(uint4*)(Vs + r * FP + d4) = v4;
        }
        __syncthreads();

        // ---- S = Q @ K^T  (warp: 16 x 64) ----
        float s[8][4];
        #pragma unroll
        for (int nt = 0; nt < 8; nt++)
            #pragma unroll
            for (int r = 0; r < 4; r++) s[nt][r] = 0.f;

        #pragma unroll
        for (int kk = 0; kk < 8; kk++) {
            uint2 qlo = *(const uint2*)(Qs + (qrow + g) * FP + kk * 8 + 2 * t);
            uint2 qhi = *(const uint2*)(Qs + (qrow + g + 8) * FP + kk * 8 + 2 * t);
            #pragma unroll
            for (int nt = 0; nt < 8; nt++) {
                uint2 kb = *(const uint2*)(Ks + (nt * 8 + g) * FP + kk * 8 + 2 * t);
                mma_tf32(s[nt], qlo.x, qhi.x, qlo.y, qhi.y, kb.x, kb.y);
            }
        }

        // ---- mask + online softmax (fp32), write P permuted ----
        const int pc0 = pos8(2 * t);   // permuted positions for cols 2t, 2t+1
        #pragma unroll
        for (int half = 0; half < 2; half++) {
            const int r0 = half * 2;
            int rowg = qt * 128 + qrow + g + half * 8;
            size_t mbase = ((size_t)b * T_ + rowg) * T_ + kt * 64;

            #pragma unroll
            for (int nt = 0; nt < 8; nt++) {
                int col = nt * 8 + 2 * t;
                int mv0, mv1;
                if (is_byte) {
                    uchar2 u = *(const uchar2*)(mask_b + mbase + col);
                    mv0 = u.x; mv1 = u.y;
                } else {
                    int2 u = *(const int2*)(mask_w + mbase + col);
                    mv0 = u.x; mv1 = u.y;
                }
                if (mv0 == 0) s[nt][r0 + 0] = -3.402823466e38f;
                if (mv1 == 0) s[nt][r0 + 1] = -3.402823466e38f;
            }

            float mx = -INFINITY;
            #pragma unroll
            for (int nt = 0; nt < 8; nt++)
                mx = fmaxf(mx, fmaxf(s[nt][r0], s[nt][r0 + 1]));
            mx = fmaxf(mx, __shfl_xor_sync(0xffffffffu, mx, 1));
            mx = fmaxf(mx, __shfl_xor_sync(0xffffffffu, mx, 2));

            float mnew = fmaxf(m_i[half], mx);
            float corr = __expf(m_i[half] - mnew);
            float rs = 0.f;
            #pragma unroll
            for (int nt = 0; nt < 8; nt++) {
                float p0 = __expf(s[nt][r0] - mnew);
                float p1 = __expf(s[nt][r0 + 1] - mnew);
                rs += p0 + p1;
                s[nt][r0] = p0; s[nt][r0 + 1] = p1;
            }
            rs += __shfl_xor_sync(0xffffffffu, rs, 1);
            rs += __shfl_xor_sync(0xffffffffu, rs, 2);
            l_i[half] = l_i[half] * corr + rs;
            m_i[half] = mnew;
            #pragma unroll
            for (int nt = 0; nt < 8; nt++) {
                o[nt][r0] *= corr; o[nt][r0 + 1] *= corr;
                unsigned* pp = Ps + (qrow + g + half * 8) * FP + nt * 8 + pc0;
                pp[0] = f2tf(s[nt][r0]);
                pp[2] = f2tf(s[nt][r0 + 1]);
            }
        }
        __syncwarp();

        // ---- O += P @ V  (warp: 16 x 64, k = 64) ----
        #pragma unroll
        for (int kk = 0; kk < 8; kk++) {
            uint2 plo = *(const uint2*)(Ps + (qrow + g) * FP + kk * 8 + 2 * t);
            uint2 phi = *(const uint2*)(Ps + (qrow + g + 8) * FP + kk * 8 + 2 * t);
            #pragma unroll
            for (int nt = 0; nt < 8; nt++) {
                unsigned b0 = Vs[(kk * 8 + t) * FP + nt * 8 + g];
                unsigned b1 = Vs[(kk * 8 + t + 4) * FP + nt * 8 + g];
                mma_tf32(o[nt], plo.x, phi.x, plo.y, phi.y, b0, b1);
            }
        }
    }

    // Epilogue: normalize, write z[b,t,h,d]
    #pragma unroll
    for (int half = 0; half < 2; half++) {
        float inv = 1.f / l_i[half];
        int rowg = qt * 128 + qrow + g + half * 8;
        #pragma unroll
        for (int nt = 0; nt < 8; nt++) {
            float2 ov = make_float2(o[nt][half * 2] * inv,
                                    o[nt][half * 2 + 1] * inv);
            *(float2*)(g_z + (size_t)(b * T_ + rowg) * N_ + h * D_ + nt * 8 + 2 * t) = ov;
        }
    }
}

#define ATTN_SMEM ((128 * FP + 64 * FP + 64 * FP + 128 * FP) * 4)

// ---------------------------------------------------------------------------
extern "C" void kernel_launch(void* const* d_in, const int* in_sizes, int n_in,
                              void* d_out, int out_size)
{
    const float* embed = (const float*)d_in[0];
    const void*  mask  = d_in[1];
    const float* Wq = (const float*)d_in[2]; const float* bq = (const float*)d_in[3];
    const float* Wk = (const float*)d_in[4]; const float* bk = (const float*)d_in[5];
    const float* Wv = (const float*)d_in[6]; const float* bv = (const float*)d_in[7];
    const float* Wz = (const float*)d_in[8]; const float* bz = (const float*)d_in[9];
    float* out = (float*)d_out;

    float *q, *k, *v, *z, *wt;
    cudaGetSymbolAddress((void**)&q, g_q);
    cudaGetSymbolAddress((void**)&k, g_k);
    cudaGetSymbolAddress((void**)&v, g_v);
    cudaGetSymbolAddress((void**)&z, g_z);
    cudaGetSymbolAddress((void**)&wt, g_wt);

    detect_mask_kernel<<<1, 256>>>((const unsigned int*)mask);
    transpose4<<<dim3(32, 32, 4), dim3(32, 8)>>>(Wq, Wk, Wv, Wz, wt);

    cudaFuncSetAttribute(gemm_qkv, cudaFuncAttributeMaxDynamicSharedMemorySize,
                         GEMM_SMEM);
    cudaFuncSetAttribute(gemm_one, cudaFuncAttributeMaxDynamicSharedMemorySize,
                         GEMM_SMEM);
    gemm_qkv<<<dim3(N_ / 128, M_ / 128, 3), 256, GEMM_SMEM>>>(
        embed, wt, bq, bk, bv, q, k, v);

    cudaFuncSetAttribute(flash_attn_tc,
                         cudaFuncAttributeMaxDynamicSharedMemorySize, ATTN_SMEM);
    flash_attn_tc<<<dim3(T_ / 128, H_, B_), 256, ATTN_SMEM>>>(mask);

    gemm_one<<<dim3(N_ / 128, M_ / 128), 256, GEMM_SMEM>>>(
        z, wt + 3ull * 1024 * 1024, bz, out);
}